// round 1
// baseline (speedup 1.0000x reference)
#include <cuda_runtime.h>

#define D 64
#define NT_MAX 300000
#define NU_MAX 300000
#define ND_MAX 100000

// ---------------- scratch (static __device__, no allocation) ----------------
__device__ float g_wh_a[(size_t)NT_MAX * D];   // features @ W[1]  (t2u proj)
__device__ float g_wh_b[(size_t)NT_MAX * D];   // features @ W[3]  (t2d proj)
__device__ float g_wh_c[(size_t)NU_MAX * D];   // h_u @ W1[0]      (u2t proj)
__device__ float g_wh_d[(size_t)ND_MAX * D];   // h_d @ W1[2]      (d2t proj)
__device__ float g_acc_u[(size_t)NU_MAX * D];
__device__ float g_acc_d[(size_t)ND_MAX * D];
__device__ float g_acc_t1[(size_t)NT_MAX * D];
__device__ float g_acc_t2[(size_t)NT_MAX * D];
__device__ float g_h_u[(size_t)NU_MAX * D];
__device__ float g_h_d[(size_t)ND_MAX * D];
__device__ int   g_cnt_u[NU_MAX];
__device__ int   g_cnt_d[ND_MAX];
__device__ int   g_cnt_t1[NT_MAX];
__device__ int   g_cnt_t2[NT_MAX];

// ---------------- kernels ----------------

// Y[n,64] = X[n,64] @ W[64,64] + b[64]
__global__ __launch_bounds__(256) void gemm64(const float* __restrict__ X,
                                              const float* __restrict__ W,
                                              const float* __restrict__ B,
                                              float* __restrict__ Y, int n)
{
    __shared__ float Wsh[D * D];
    __shared__ float Bsh[D];
    for (int i = threadIdx.x; i < D * D; i += 256) Wsh[i] = W[i];
    if (threadIdx.x < D) Bsh[threadIdx.x] = B[threadIdx.x];
    __syncthreads();

    int row = blockIdx.x * 256 + threadIdx.x;
    if (row >= n) return;

    float acc[D];
#pragma unroll
    for (int c = 0; c < D; ++c) acc[c] = Bsh[c];

    const float4* xr = reinterpret_cast<const float4*>(X + (size_t)row * D);
    for (int k4 = 0; k4 < D / 4; ++k4) {
        float4 xv = xr[k4];
#pragma unroll
        for (int kk = 0; kk < 4; ++kk) {
            float xk = (kk == 0) ? xv.x : (kk == 1) ? xv.y : (kk == 2) ? xv.z : xv.w;
            const float4* wr = reinterpret_cast<const float4*>(Wsh + (k4 * 4 + kk) * D);
#pragma unroll
            for (int c4 = 0; c4 < D / 4; ++c4) {
                float4 wv = wr[c4];
                acc[c4 * 4 + 0] += xk * wv.x;
                acc[c4 * 4 + 1] += xk * wv.y;
                acc[c4 * 4 + 2] += xk * wv.z;
                acc[c4 * 4 + 3] += xk * wv.w;
            }
        }
    }

    float4* yr = reinterpret_cast<float4*>(Y + (size_t)row * D);
#pragma unroll
    for (int c4 = 0; c4 < D / 4; ++c4)
        yr[c4] = make_float4(acc[c4 * 4 + 0], acc[c4 * 4 + 1],
                             acc[c4 * 4 + 2], acc[c4 * 4 + 3]);
}

// in-degree histogram
__global__ void count_k(const int* __restrict__ dst, int* __restrict__ cnt, int e)
{
    int i = blockIdx.x * blockDim.x + threadIdx.x;
    if (i < e) atomicAdd(&cnt[dst[i]], 1);
}

// per edge: ACC[dst] += WH[src]  (16 threads/edge, vector f32 reductions)
__global__ __launch_bounds__(256) void scatter_k(const float* __restrict__ WH,
                                                 const int* __restrict__ src,
                                                 const int* __restrict__ dst,
                                                 float* __restrict__ ACC, int e)
{
    int idx  = blockIdx.x * 256 + threadIdx.x;
    int edge = idx >> 4;
    int lane = idx & 15;
    if (edge >= e) return;

    int s = __ldg(&src[edge]);
    int d = __ldg(&dst[edge]);
    float4 v = __ldg(reinterpret_cast<const float4*>(WH + (size_t)s * D) + lane);
    float* q = ACC + (size_t)d * D + (size_t)lane * 4;
    asm volatile("red.global.add.v4.f32 [%0], {%1, %2, %3, %4};"
                 :: "l"(q), "f"(v.x), "f"(v.y), "f"(v.z), "f"(v.w)
                 : "memory");
}

__device__ __forceinline__ float lrelu(float x) { return x > 0.0f ? x : 0.01f * x; }

// H = leaky_relu(ACC / max(cnt,1))   (16 threads/row)
__global__ __launch_bounds__(256) void norm_lrelu_k(const float* __restrict__ ACC,
                                                    const int* __restrict__ cnt,
                                                    float* __restrict__ H, int n)
{
    int idx  = blockIdx.x * 256 + threadIdx.x;
    int row  = idx >> 4;
    int lane = idx & 15;
    if (row >= n) return;
    int c = __ldg(&cnt[row]);
    float inv = 1.0f / (float)(c > 0 ? c : 1);
    float4 v = __ldg(reinterpret_cast<const float4*>(ACC + (size_t)row * D) + lane);
    float4 r;
    r.x = lrelu(v.x * inv);
    r.y = lrelu(v.y * inv);
    r.z = lrelu(v.z * inv);
    r.w = lrelu(v.w * inv);
    *(reinterpret_cast<float4*>(H + (size_t)row * D) + lane) = r;
}

// out[row,0:2] = (A1/max(c1,1) + A2/max(c2,1)) @ Wc + bc
__global__ __launch_bounds__(256) void final_k(const float* __restrict__ A1,
                                               const float* __restrict__ A2,
                                               const int* __restrict__ c1,
                                               const int* __restrict__ c2,
                                               const float* __restrict__ Wc,
                                               const float* __restrict__ bc,
                                               float* __restrict__ out, int n)
{
    __shared__ float Wsh[D * 2];
    __shared__ float bsh[2];
    if (threadIdx.x < D * 2) Wsh[threadIdx.x] = Wc[threadIdx.x];
    if (threadIdx.x < 2) bsh[threadIdx.x] = bc[threadIdx.x];
    __syncthreads();

    int row = blockIdx.x * 256 + threadIdx.x;
    if (row >= n) return;

    int cc1 = __ldg(&c1[row]);
    int cc2 = __ldg(&c2[row]);
    float inv1 = 1.0f / (float)(cc1 > 0 ? cc1 : 1);
    float inv2 = 1.0f / (float)(cc2 > 0 ? cc2 : 1);

    const float4* a1 = reinterpret_cast<const float4*>(A1 + (size_t)row * D);
    const float4* a2 = reinterpret_cast<const float4*>(A2 + (size_t)row * D);

    float o0 = bsh[0], o1 = bsh[1];
#pragma unroll
    for (int i4 = 0; i4 < D / 4; ++i4) {
        float4 v1 = __ldg(a1 + i4);
        float4 v2 = __ldg(a2 + i4);
        float m;
        m = v1.x * inv1 + v2.x * inv2; o0 += m * Wsh[(i4 * 4 + 0) * 2]; o1 += m * Wsh[(i4 * 4 + 0) * 2 + 1];
        m = v1.y * inv1 + v2.y * inv2; o0 += m * Wsh[(i4 * 4 + 1) * 2]; o1 += m * Wsh[(i4 * 4 + 1) * 2 + 1];
        m = v1.z * inv1 + v2.z * inv2; o0 += m * Wsh[(i4 * 4 + 2) * 2]; o1 += m * Wsh[(i4 * 4 + 2) * 2 + 1];
        m = v1.w * inv1 + v2.w * inv2; o0 += m * Wsh[(i4 * 4 + 3) * 2]; o1 += m * Wsh[(i4 * 4 + 3) * 2 + 1];
    }
    out[(size_t)row * 2 + 0] = o0;
    out[(size_t)row * 2 + 1] = o1;
}

// ---------------- launch ----------------

static inline int cdiv(long long a, int b) { return (int)((a + b - 1) / b); }

extern "C" void kernel_launch(void* const* d_in, const int* in_sizes, int n_in,
                              void* d_out, int out_size)
{
    const float* features   = (const float*)d_in[0];
    const float* emb_user   = (const float*)d_in[1];  (void)emb_user;   // layer-0 u2t path dead
    const float* emb_device = (const float*)d_in[2];  (void)emb_device; // layer-0 d2t path dead
    const float* W0 = (const float*)d_in[3];
    const float* b0 = (const float*)d_in[4];
    const float* W1 = (const float*)d_in[5];
    const float* b1 = (const float*)d_in[6];
    const float* Wc = (const float*)d_in[7];
    const float* bc = (const float*)d_in[8];
    const int* src_u2t = (const int*)d_in[9];
    const int* dst_u2t = (const int*)d_in[10];
    const int* src_t2u = (const int*)d_in[11];
    const int* dst_t2u = (const int*)d_in[12];
    const int* src_d2t = (const int*)d_in[13];
    const int* dst_d2t = (const int*)d_in[14];
    const int* src_t2d = (const int*)d_in[15];
    const int* dst_t2d = (const int*)d_in[16];

    const int nt = in_sizes[0] / D;
    const int nu = in_sizes[1] / D;
    const int nd = in_sizes[2] / D;
    const int e_u2t = in_sizes[9];
    const int e_t2u = in_sizes[11];
    const int e_d2t = in_sizes[13];
    const int e_t2d = in_sizes[15];

    float *wh_a, *wh_b, *wh_c, *wh_d, *acc_u, *acc_d, *acc_t1, *acc_t2, *h_u, *h_d;
    int *cnt_u, *cnt_d, *cnt_t1, *cnt_t2;
    cudaGetSymbolAddress((void**)&wh_a, g_wh_a);
    cudaGetSymbolAddress((void**)&wh_b, g_wh_b);
    cudaGetSymbolAddress((void**)&wh_c, g_wh_c);
    cudaGetSymbolAddress((void**)&wh_d, g_wh_d);
    cudaGetSymbolAddress((void**)&acc_u, g_acc_u);
    cudaGetSymbolAddress((void**)&acc_d, g_acc_d);
    cudaGetSymbolAddress((void**)&acc_t1, g_acc_t1);
    cudaGetSymbolAddress((void**)&acc_t2, g_acc_t2);
    cudaGetSymbolAddress((void**)&h_u, g_h_u);
    cudaGetSymbolAddress((void**)&h_d, g_h_d);
    cudaGetSymbolAddress((void**)&cnt_u, g_cnt_u);
    cudaGetSymbolAddress((void**)&cnt_d, g_cnt_d);
    cudaGetSymbolAddress((void**)&cnt_t1, g_cnt_t1);
    cudaGetSymbolAddress((void**)&cnt_t2, g_cnt_t2);

    cudaStream_t s = 0;

    // zero accumulators + counts
    cudaMemsetAsync(acc_u,  0, (size_t)nu * D * sizeof(float), s);
    cudaMemsetAsync(acc_d,  0, (size_t)nd * D * sizeof(float), s);
    cudaMemsetAsync(acc_t1, 0, (size_t)nt * D * sizeof(float), s);
    cudaMemsetAsync(acc_t2, 0, (size_t)nt * D * sizeof(float), s);
    cudaMemsetAsync(cnt_u,  0, (size_t)nu * sizeof(int), s);
    cudaMemsetAsync(cnt_d,  0, (size_t)nd * sizeof(int), s);
    cudaMemsetAsync(cnt_t1, 0, (size_t)nt * sizeof(int), s);
    cudaMemsetAsync(cnt_t2, 0, (size_t)nt * sizeof(int), s);

    // in-degree counts (fixed across layers)
    count_k<<<cdiv(e_t2u, 256), 256, 0, s>>>(dst_t2u, cnt_u, e_t2u);
    count_k<<<cdiv(e_t2d, 256), 256, 0, s>>>(dst_t2d, cnt_d, e_t2d);
    count_k<<<cdiv(e_u2t, 256), 256, 0, s>>>(dst_u2t, cnt_t1, e_u2t);
    count_k<<<cdiv(e_d2t, 256), 256, 0, s>>>(dst_d2t, cnt_t2, e_d2t);

    // ---- layer 0 (only paths feeding the final output: t2u, t2d) ----
    gemm64<<<cdiv(nt, 256), 256, 0, s>>>(features, W0 + 1 * D * D, b0 + 1 * D, wh_a, nt);
    gemm64<<<cdiv(nt, 256), 256, 0, s>>>(features, W0 + 3 * D * D, b0 + 3 * D, wh_b, nt);

    scatter_k<<<cdiv((long long)e_t2u * 16, 256), 256, 0, s>>>(wh_a, src_t2u, dst_t2u, acc_u, e_t2u);
    scatter_k<<<cdiv((long long)e_t2d * 16, 256), 256, 0, s>>>(wh_b, src_t2d, dst_t2d, acc_d, e_t2d);

    norm_lrelu_k<<<cdiv((long long)nu * 16, 256), 256, 0, s>>>(acc_u, cnt_u, h_u, nu);
    norm_lrelu_k<<<cdiv((long long)nd * 16, 256), 256, 0, s>>>(acc_d, cnt_d, h_d, nd);

    // ---- layer 1 (only u2t, d2t feed new_t) ----
    gemm64<<<cdiv(nu, 256), 256, 0, s>>>(h_u, W1 + 0 * D * D, b1 + 0 * D, wh_c, nu);
    gemm64<<<cdiv(nd, 256), 256, 0, s>>>(h_d, W1 + 2 * D * D, b1 + 2 * D, wh_d, nd);

    scatter_k<<<cdiv((long long)e_u2t * 16, 256), 256, 0, s>>>(wh_c, src_u2t, dst_u2t, acc_t1, e_u2t);
    scatter_k<<<cdiv((long long)e_d2t * 16, 256), 256, 0, s>>>(wh_d, src_d2t, dst_d2t, acc_t2, e_d2t);

    // ---- fused normalize + classifier ----
    final_k<<<cdiv(nt, 256), 256, 0, s>>>(acc_t1, acc_t2, cnt_t1, cnt_t2, Wc, bc,
                                          (float*)d_out, nt);
}

// round 3
// speedup vs baseline: 1.3510x; 1.3510x over previous
#include <cuda_runtime.h>

#define D 64
#define NT_MAX 300000
#define NU_MAX 300000
#define ND_MAX 100000
#define E_MAX  2000000
#define SCAN_B 1024
#define MAX_SCAN_BLOCKS 512

// ---------------- scratch (static __device__, no allocation) ----------------
__device__ float g_wh_a[(size_t)NT_MAX * D];   // features @ W0[1]  (t2u proj)
__device__ float g_wh_b[(size_t)NT_MAX * D];   // features @ W0[3]  (t2d proj)
__device__ float g_wh_c[(size_t)NU_MAX * D];   // h_u @ W1[0]       (u2t proj)
__device__ float g_wh_d[(size_t)ND_MAX * D];   // h_d @ W1[2]       (d2t proj)
__device__ float g_h_u[(size_t)NU_MAX * D];
__device__ float g_h_d[(size_t)ND_MAX * D];

__device__ int g_eidx_t2u[E_MAX];
__device__ int g_eidx_t2d[E_MAX];
__device__ int g_eidx_u2t[E_MAX];
__device__ int g_eidx_d2t[E_MAX];

__device__ int g_cnt_u[NU_MAX],  g_off_u[NU_MAX],  g_cur_u[NU_MAX];
__device__ int g_cnt_d[ND_MAX],  g_off_d[ND_MAX],  g_cur_d[ND_MAX];
__device__ int g_cnt_t1[NT_MAX], g_off_t1[NT_MAX], g_cur_t1[NT_MAX];
__device__ int g_cnt_t2[NT_MAX], g_off_t2[NT_MAX], g_cur_t2[NT_MAX];
__device__ int g_bsum[MAX_SCAN_BLOCKS];

// ---------------- kernels ----------------

// Y[n,64] = X[n,64] @ W[64,64] + b[64]
__global__ __launch_bounds__(256) void gemm64(const float* __restrict__ X,
                                              const float* __restrict__ W,
                                              const float* __restrict__ B,
                                              float* __restrict__ Y, int n)
{
    __shared__ float Wsh[D * D];
    __shared__ float Bsh[D];
    for (int i = threadIdx.x; i < D * D; i += 256) Wsh[i] = W[i];
    if (threadIdx.x < D) Bsh[threadIdx.x] = B[threadIdx.x];
    __syncthreads();

    int row = blockIdx.x * 256 + threadIdx.x;
    if (row >= n) return;

    float acc[D];
#pragma unroll
    for (int c = 0; c < D; ++c) acc[c] = Bsh[c];

    const float4* xr = reinterpret_cast<const float4*>(X + (size_t)row * D);
    for (int k4 = 0; k4 < D / 4; ++k4) {
        float4 xv = xr[k4];
#pragma unroll
        for (int kk = 0; kk < 4; ++kk) {
            float xk = (kk == 0) ? xv.x : (kk == 1) ? xv.y : (kk == 2) ? xv.z : xv.w;
            const float4* wr = reinterpret_cast<const float4*>(Wsh + (k4 * 4 + kk) * D);
#pragma unroll
            for (int c4 = 0; c4 < D / 4; ++c4) {
                float4 wv = wr[c4];
                acc[c4 * 4 + 0] += xk * wv.x;
                acc[c4 * 4 + 1] += xk * wv.y;
                acc[c4 * 4 + 2] += xk * wv.z;
                acc[c4 * 4 + 3] += xk * wv.w;
            }
        }
    }

    float4* yr = reinterpret_cast<float4*>(Y + (size_t)row * D);
#pragma unroll
    for (int c4 = 0; c4 < D / 4; ++c4)
        yr[c4] = make_float4(acc[c4 * 4 + 0], acc[c4 * 4 + 1],
                             acc[c4 * 4 + 2], acc[c4 * 4 + 3]);
}

// in-degree histogram (grid-stride)
__global__ __launch_bounds__(256) void count_k(const int* __restrict__ dst,
                                               int* __restrict__ cnt, int e)
{
    for (int i = blockIdx.x * blockDim.x + threadIdx.x; i < e;
         i += gridDim.x * blockDim.x)
        atomicAdd(&cnt[dst[i]], 1);
}

// block-level exclusive scan (Hillis-Steele in shared)
__global__ __launch_bounds__(SCAN_B) void scan_blocks_k(const int* __restrict__ cnt,
                                                        int* __restrict__ off,
                                                        int* __restrict__ bsum, int n)
{
    __shared__ int sh[SCAN_B];
    int tid = threadIdx.x;
    int i = blockIdx.x * SCAN_B + tid;
    int v = (i < n) ? cnt[i] : 0;
    sh[tid] = v;
    __syncthreads();
    for (int o = 1; o < SCAN_B; o <<= 1) {
        int t = (tid >= o) ? sh[tid - o] : 0;
        __syncthreads();
        sh[tid] += t;
        __syncthreads();
    }
    if (i < n) off[i] = sh[tid] - v;
    if (tid == SCAN_B - 1) bsum[blockIdx.x] = sh[tid];
}

__global__ __launch_bounds__(SCAN_B) void scan_sums_k(int* bsum, int nb)
{
    __shared__ int sh[SCAN_B];
    int tid = threadIdx.x;
    int v = (tid < nb) ? bsum[tid] : 0;
    sh[tid] = v;
    __syncthreads();
    for (int o = 1; o < SCAN_B; o <<= 1) {
        int t = (tid >= o) ? sh[tid - o] : 0;
        __syncthreads();
        sh[tid] += t;
        __syncthreads();
    }
    if (tid < nb) bsum[tid] = sh[tid] - v;
}

__global__ __launch_bounds__(SCAN_B) void scan_add_k(int* off, const int* __restrict__ bsum, int n)
{
    int i = blockIdx.x * SCAN_B + threadIdx.x;
    if (i < n) off[i] += bsum[blockIdx.x];
}

// place each edge's src into its destination's CSR slot (grid-stride)
__global__ __launch_bounds__(256) void fill_k(const int* __restrict__ src,
                                              const int* __restrict__ dst,
                                              const int* __restrict__ off,
                                              int* __restrict__ cur,
                                              int* __restrict__ eidx, int e)
{
    for (int i = blockIdx.x * blockDim.x + threadIdx.x; i < e;
         i += gridDim.x * blockDim.x) {
        int d = dst[i];
        int p = atomicAdd(&cur[d], 1);
        eidx[off[d] + p] = src[i];
    }
}

__device__ __forceinline__ float lrelu(float x) { return x > 0.0f ? x : 0.01f * x; }

__device__ __forceinline__ float4 gather_row(const float4* __restrict__ base,
                                             const int* __restrict__ eidx,
                                             int beg, int deg, int lane)
{
    float4 acc = make_float4(0.f, 0.f, 0.f, 0.f);
    int i = 0;
    for (; i + 2 <= deg; i += 2) {
        int s0 = __ldg(&eidx[beg + i]);
        int s1 = __ldg(&eidx[beg + i + 1]);
        float4 a = __ldg(base + (size_t)s0 * 16 + lane);
        float4 b = __ldg(base + (size_t)s1 * 16 + lane);
        acc.x += a.x + b.x; acc.y += a.y + b.y;
        acc.z += a.z + b.z; acc.w += a.w + b.w;
    }
    if (i < deg) {
        int s0 = __ldg(&eidx[beg + i]);
        float4 a = __ldg(base + (size_t)s0 * 16 + lane);
        acc.x += a.x; acc.y += a.y; acc.z += a.z; acc.w += a.w;
    }
    return acc;
}

// H[row] = leaky_relu(mean of WH[src] over in-edges)   (16 lanes/row)
__global__ __launch_bounds__(256) void gather_mean_lrelu_k(const float* __restrict__ WH,
                                                           const int* __restrict__ off,
                                                           const int* __restrict__ cnt,
                                                           const int* __restrict__ eidx,
                                                           float* __restrict__ H, int n)
{
    int idx  = blockIdx.x * 256 + threadIdx.x;
    int row  = idx >> 4;
    int lane = idx & 15;
    if (row >= n) return;

    int beg = __ldg(&off[row]);
    int deg = __ldg(&cnt[row]);
    float4 acc = gather_row(reinterpret_cast<const float4*>(WH), eidx, beg, deg, lane);
    float inv = 1.0f / (float)(deg > 0 ? deg : 1);
    float4 r;
    r.x = lrelu(acc.x * inv);
    r.y = lrelu(acc.y * inv);
    r.z = lrelu(acc.z * inv);
    r.w = lrelu(acc.w * inv);
    *(reinterpret_cast<float4*>(H + (size_t)row * D) + lane) = r;
}

// Fused layer-1 aggregation + classifier:
// out[row] = (mean_u2t wh_c + mean_d2t wh_d) @ Wc + bc   (16 lanes/row)
__global__ __launch_bounds__(256) void final_fused_k(const float* __restrict__ WHC,
                                                     const float* __restrict__ WHD,
                                                     const int* __restrict__ off1,
                                                     const int* __restrict__ cnt1,
                                                     const int* __restrict__ eidx1,
                                                     const int* __restrict__ off2,
                                                     const int* __restrict__ cnt2,
                                                     const int* __restrict__ eidx2,
                                                     const float* __restrict__ Wc,
                                                     const float* __restrict__ bc,
                                                     float* __restrict__ out, int n)
{
    __shared__ float W0s[D], W1s[D];
    __shared__ float bsh[2];
    if (threadIdx.x < D) {
        W0s[threadIdx.x] = Wc[threadIdx.x * 2 + 0];
        W1s[threadIdx.x] = Wc[threadIdx.x * 2 + 1];
    }
    if (threadIdx.x < 2) bsh[threadIdx.x] = bc[threadIdx.x];
    __syncthreads();

    int idx  = blockIdx.x * 256 + threadIdx.x;
    int row  = idx >> 4;
    int lane = idx & 15;
    if (row >= n) return;

    int beg1 = __ldg(&off1[row]);
    int deg1 = __ldg(&cnt1[row]);
    int beg2 = __ldg(&off2[row]);
    int deg2 = __ldg(&cnt2[row]);

    float4 a1 = gather_row(reinterpret_cast<const float4*>(WHC), eidx1, beg1, deg1, lane);
    float4 a2 = gather_row(reinterpret_cast<const float4*>(WHD), eidx2, beg2, deg2, lane);
    float inv1 = 1.0f / (float)(deg1 > 0 ? deg1 : 1);
    float inv2 = 1.0f / (float)(deg2 > 0 ? deg2 : 1);

    int c = lane * 4;
    float m0 = a1.x * inv1 + a2.x * inv2;
    float m1 = a1.y * inv1 + a2.y * inv2;
    float m2 = a1.z * inv1 + a2.z * inv2;
    float m3 = a1.w * inv1 + a2.w * inv2;

    float o0 = m0 * W0s[c] + m1 * W0s[c + 1] + m2 * W0s[c + 2] + m3 * W0s[c + 3];
    float o1 = m0 * W1s[c] + m1 * W1s[c + 1] + m2 * W1s[c + 2] + m3 * W1s[c + 3];

#pragma unroll
    for (int o = 8; o > 0; o >>= 1) {
        o0 += __shfl_down_sync(0xffffffffu, o0, o, 16);
        o1 += __shfl_down_sync(0xffffffffu, o1, o, 16);
    }
    if (lane == 0) {
        out[(size_t)row * 2 + 0] = o0 + bsh[0];
        out[(size_t)row * 2 + 1] = o1 + bsh[1];
    }
}

// ---------------- launch ----------------

static inline int cdiv(long long a, int b) { return (int)((a + b - 1) / b); }

static void build_csr(const int* dst, int* cnt, int* off, int* cur, int* bsum,
                      int* eidx, const int* src, int n, int e, cudaStream_t s)
{
    count_k<<<1184, 256, 0, s>>>(dst, cnt, e);
    int nb = cdiv(n, SCAN_B);
    scan_blocks_k<<<nb, SCAN_B, 0, s>>>(cnt, off, bsum, n);
    scan_sums_k<<<1, SCAN_B, 0, s>>>(bsum, nb);
    scan_add_k<<<nb, SCAN_B, 0, s>>>(off, bsum, n);
    fill_k<<<1184, 256, 0, s>>>(src, dst, off, cur, eidx, e);
}

extern "C" void kernel_launch(void* const* d_in, const int* in_sizes, int n_in,
                              void* d_out, int out_size)
{
    const float* features = (const float*)d_in[0];
    const float* W0 = (const float*)d_in[3];
    const float* b0 = (const float*)d_in[4];
    const float* W1 = (const float*)d_in[5];
    const float* b1 = (const float*)d_in[6];
    const float* Wc = (const float*)d_in[7];
    const float* bc = (const float*)d_in[8];
    const int* src_u2t = (const int*)d_in[9];
    const int* dst_u2t = (const int*)d_in[10];
    const int* src_t2u = (const int*)d_in[11];
    const int* dst_t2u = (const int*)d_in[12];
    const int* src_d2t = (const int*)d_in[13];
    const int* dst_d2t = (const int*)d_in[14];
    const int* src_t2d = (const int*)d_in[15];
    const int* dst_t2d = (const int*)d_in[16];

    const int nt = in_sizes[0] / D;
    const int nu = in_sizes[1] / D;
    const int nd = in_sizes[2] / D;
    const int e_u2t = in_sizes[9];
    const int e_t2u = in_sizes[11];
    const int e_d2t = in_sizes[13];
    const int e_t2d = in_sizes[15];

    float *wh_a, *wh_b, *wh_c, *wh_d, *h_u, *h_d;
    int *eidx_t2u, *eidx_t2d, *eidx_u2t, *eidx_d2t;
    int *cnt_u, *off_u, *cur_u, *cnt_d, *off_d, *cur_d;
    int *cnt_t1, *off_t1, *cur_t1, *cnt_t2, *off_t2, *cur_t2, *bsum;
    cudaGetSymbolAddress((void**)&wh_a, g_wh_a);
    cudaGetSymbolAddress((void**)&wh_b, g_wh_b);
    cudaGetSymbolAddress((void**)&wh_c, g_wh_c);
    cudaGetSymbolAddress((void**)&wh_d, g_wh_d);
    cudaGetSymbolAddress((void**)&h_u, g_h_u);
    cudaGetSymbolAddress((void**)&h_d, g_h_d);
    cudaGetSymbolAddress((void**)&eidx_t2u, g_eidx_t2u);
    cudaGetSymbolAddress((void**)&eidx_t2d, g_eidx_t2d);
    cudaGetSymbolAddress((void**)&eidx_u2t, g_eidx_u2t);
    cudaGetSymbolAddress((void**)&eidx_d2t, g_eidx_d2t);
    cudaGetSymbolAddress((void**)&cnt_u, g_cnt_u);
    cudaGetSymbolAddress((void**)&off_u, g_off_u);
    cudaGetSymbolAddress((void**)&cur_u, g_cur_u);
    cudaGetSymbolAddress((void**)&cnt_d, g_cnt_d);
    cudaGetSymbolAddress((void**)&off_d, g_off_d);
    cudaGetSymbolAddress((void**)&cur_d, g_cur_d);
    cudaGetSymbolAddress((void**)&cnt_t1, g_cnt_t1);
    cudaGetSymbolAddress((void**)&off_t1, g_off_t1);
    cudaGetSymbolAddress((void**)&cur_t1, g_cur_t1);
    cudaGetSymbolAddress((void**)&cnt_t2, g_cnt_t2);
    cudaGetSymbolAddress((void**)&off_t2, g_off_t2);
    cudaGetSymbolAddress((void**)&cur_t2, g_cur_t2);
    cudaGetSymbolAddress((void**)&bsum, g_bsum);

    cudaStream_t s = 0;

    // zero counts + cursors (small)
    cudaMemsetAsync(cnt_u, 0, (size_t)nu * sizeof(int), s);
    cudaMemsetAsync(cur_u, 0, (size_t)nu * sizeof(int), s);
    cudaMemsetAsync(cnt_d, 0, (size_t)nd * sizeof(int), s);
    cudaMemsetAsync(cur_d, 0, (size_t)nd * sizeof(int), s);
    cudaMemsetAsync(cnt_t1, 0, (size_t)nt * sizeof(int), s);
    cudaMemsetAsync(cur_t1, 0, (size_t)nt * sizeof(int), s);
    cudaMemsetAsync(cnt_t2, 0, (size_t)nt * sizeof(int), s);
    cudaMemsetAsync(cur_t2, 0, (size_t)nt * sizeof(int), s);

    // projections for layer 0 (only live paths: t2u, t2d)
    gemm64<<<cdiv(nt, 256), 256, 0, s>>>(features, W0 + 1 * D * D, b0 + 1 * D, wh_a, nt);
    gemm64<<<cdiv(nt, 256), 256, 0, s>>>(features, W0 + 3 * D * D, b0 + 3 * D, wh_b, nt);

    // CSR builds (serialized on stream; bsum reused)
    build_csr(dst_t2u, cnt_u, off_u, cur_u, bsum, eidx_t2u, src_t2u, nu, e_t2u, s);
    build_csr(dst_t2d, cnt_d, off_d, cur_d, bsum, eidx_t2d, src_t2d, nd, e_t2d, s);
    build_csr(dst_u2t, cnt_t1, off_t1, cur_t1, bsum, eidx_u2t, src_u2t, nt, e_u2t, s);
    build_csr(dst_d2t, cnt_t2, off_t2, cur_t2, bsum, eidx_d2t, src_d2t, nt, e_d2t, s);

    // layer 0 aggregation: gather + mean + leaky_relu, fused
    gather_mean_lrelu_k<<<cdiv((long long)nu * 16, 256), 256, 0, s>>>(wh_a, off_u, cnt_u, eidx_t2u, h_u, nu);
    gather_mean_lrelu_k<<<cdiv((long long)nd * 16, 256), 256, 0, s>>>(wh_b, off_d, cnt_d, eidx_t2d, h_d, nd);

    // layer 1 projections (only u2t, d2t feed new_t)
    gemm64<<<cdiv(nu, 256), 256, 0, s>>>(h_u, W1 + 0 * D * D, b1 + 0 * D, wh_c, nu);
    gemm64<<<cdiv(nd, 256), 256, 0, s>>>(h_d, W1 + 2 * D * D, b1 + 2 * D, wh_d, nd);

    // fused layer-1 aggregation + classifier
    final_fused_k<<<cdiv((long long)nt * 16, 256), 256, 0, s>>>(
        wh_c, wh_d, off_t1, cnt_t1, eidx_u2t, off_t2, cnt_t2, eidx_d2t,
        Wc, bc, (float*)d_out, nt);
}

// round 4
// speedup vs baseline: 2.5178x; 1.8636x over previous
#include <cuda_runtime.h>

#define D 64
#define NT_MAX 300000
#define NU_MAX 300000
#define ND_MAX 100000
#define E_MAX  2000000
#define SCAN_B 1024
#define MAX_SCAN_BLOCKS 512

// ---------------- scratch (static __device__, no allocation) ----------------
__device__ float g_mf_u[(size_t)NU_MAX * D];   // mean of features over t2u in-edges
__device__ float g_mf_d[(size_t)ND_MAX * D];   // mean of features over t2d in-edges
__device__ float2 g_z_u[NU_MAX];               // lrelu(mf_u@W0[1]+b0[1]) @ (W1[0]@Wc)
__device__ float2 g_z_d[ND_MAX];
__device__ float2 g_acc_t1[NT_MAX];            // scatter sums of z_u over u2t
__device__ float2 g_acc_t2[NT_MAX];            // scatter sums of z_d over d2t

__device__ int g_eidx_t2u[E_MAX];
__device__ int g_eidx_t2d[E_MAX];

__device__ int g_cnt_u[NU_MAX],  g_off_u[NU_MAX],  g_cur_u[NU_MAX];
__device__ int g_cnt_d[ND_MAX],  g_off_d[ND_MAX],  g_cur_d[ND_MAX];
__device__ int g_cnt_t1[NT_MAX];
__device__ int g_cnt_t2[NT_MAX];
__device__ int g_bsum[MAX_SCAN_BLOCKS];
__device__ float g_Wf[2 * D * 2];              // folded W1@Wc for u (idx 0) and d (idx 1)
__device__ float g_cvec[4];                    // cU0,cU1,cD0,cD1 = b1@Wc constants

// ---------------- kernels ----------------

// Fold classifier into layer-1 weights:
//   Wf[r][k][j] = sum_h W1[sel_r][k][h] * Wc[h][j],  sel = {0 (u2t), 2 (d2t)}
//   cvec[r*2+j] = sum_h b1[sel_r][h] * Wc[h][j]
__global__ void prep_k(const float* __restrict__ W1, const float* __restrict__ b1,
                       const float* __restrict__ Wc,
                       float* __restrict__ Wf, float* __restrict__ cvec)
{
    int tid = threadIdx.x;               // 256 threads: r(1b) k(6b) j(1b)
    int r = tid >> 7;
    int k = (tid >> 1) & 63;
    int j = tid & 1;
    int sel = (r == 0) ? 0 : 2;
    const float* w = W1 + (size_t)sel * D * D + (size_t)k * D;
    float acc = 0.f;
#pragma unroll
    for (int h = 0; h < D; ++h) acc += w[h] * Wc[h * 2 + j];
    Wf[r * D * 2 + k * 2 + j] = acc;
    if (tid < 4) {
        int rr = tid >> 1, jj = tid & 1;
        int ss = (rr == 0) ? 0 : 2;
        float c = 0.f;
        const float* bb = b1 + (size_t)ss * D;
#pragma unroll
        for (int h = 0; h < D; ++h) c += bb[h] * Wc[h * 2 + jj];
        cvec[rr * 2 + jj] = c;
    }
}

// in-degree histogram (grid-stride)
__global__ __launch_bounds__(256) void count_k(const int* __restrict__ dst,
                                               int* __restrict__ cnt, int e)
{
    for (int i = blockIdx.x * blockDim.x + threadIdx.x; i < e;
         i += gridDim.x * blockDim.x)
        atomicAdd(&cnt[dst[i]], 1);
}

// block-level exclusive scan
__global__ __launch_bounds__(SCAN_B) void scan_blocks_k(const int* __restrict__ cnt,
                                                        int* __restrict__ off,
                                                        int* __restrict__ bsum, int n)
{
    __shared__ int sh[SCAN_B];
    int tid = threadIdx.x;
    int i = blockIdx.x * SCAN_B + tid;
    int v = (i < n) ? cnt[i] : 0;
    sh[tid] = v;
    __syncthreads();
    for (int o = 1; o < SCAN_B; o <<= 1) {
        int t = (tid >= o) ? sh[tid - o] : 0;
        __syncthreads();
        sh[tid] += t;
        __syncthreads();
    }
    if (i < n) off[i] = sh[tid] - v;
    if (tid == SCAN_B - 1) bsum[blockIdx.x] = sh[tid];
}

__global__ __launch_bounds__(SCAN_B) void scan_sums_k(int* bsum, int nb)
{
    __shared__ int sh[SCAN_B];
    int tid = threadIdx.x;
    int v = (tid < nb) ? bsum[tid] : 0;
    sh[tid] = v;
    __syncthreads();
    for (int o = 1; o < SCAN_B; o <<= 1) {
        int t = (tid >= o) ? sh[tid - o] : 0;
        __syncthreads();
        sh[tid] += t;
        __syncthreads();
    }
    if (tid < nb) bsum[tid] = sh[tid] - v;
}

__global__ __launch_bounds__(SCAN_B) void scan_add_k(int* off, const int* __restrict__ bsum, int n)
{
    int i = blockIdx.x * SCAN_B + threadIdx.x;
    if (i < n) off[i] += bsum[blockIdx.x];
}

// place each edge's src into its destination's CSR slot (grid-stride)
__global__ __launch_bounds__(256) void fill_k(const int* __restrict__ src,
                                              const int* __restrict__ dst,
                                              const int* __restrict__ off,
                                              int* __restrict__ cur,
                                              int* __restrict__ eidx, int e)
{
    for (int i = blockIdx.x * blockDim.x + threadIdx.x; i < e;
         i += gridDim.x * blockDim.x) {
        int d = dst[i];
        int p = atomicAdd(&cur[d], 1);
        eidx[off[d] + p] = src[i];
    }
}

// MF[row] = mean of FEAT[src] over in-edges   (16 lanes/row)
__global__ __launch_bounds__(256) void gather_mean_k(const float* __restrict__ FEAT,
                                                     const int* __restrict__ off,
                                                     const int* __restrict__ cnt,
                                                     const int* __restrict__ eidx,
                                                     float* __restrict__ MF, int n)
{
    int idx  = blockIdx.x * 256 + threadIdx.x;
    int row  = idx >> 4;
    int lane = idx & 15;
    if (row >= n) return;

    int beg = __ldg(&off[row]);
    int deg = __ldg(&cnt[row]);
    const float4* base = reinterpret_cast<const float4*>(FEAT);
    float4 acc = make_float4(0.f, 0.f, 0.f, 0.f);
    int i = 0;
    for (; i + 2 <= deg; i += 2) {
        int s0 = __ldg(&eidx[beg + i]);
        int s1 = __ldg(&eidx[beg + i + 1]);
        float4 a = __ldg(base + (size_t)s0 * 16 + lane);
        float4 b = __ldg(base + (size_t)s1 * 16 + lane);
        acc.x += a.x + b.x; acc.y += a.y + b.y;
        acc.z += a.z + b.z; acc.w += a.w + b.w;
    }
    if (i < deg) {
        int s0 = __ldg(&eidx[beg + i]);
        float4 a = __ldg(base + (size_t)s0 * 16 + lane);
        acc.x += a.x; acc.y += a.y; acc.z += a.z; acc.w += a.w;
    }
    float inv = 1.0f / (float)(deg > 0 ? deg : 1);
    acc.x *= inv; acc.y *= inv; acc.z *= inv; acc.w *= inv;
    *(reinterpret_cast<float4*>(MF + (size_t)row * D) + lane) = acc;
}

__device__ __forceinline__ float lrelu(float x) { return x > 0.0f ? x : 0.01f * x; }

// z[row] = lrelu(MF[row] @ W0sel + b0sel*(deg>0)) @ Wf_r    (1 thread/row, 2 outputs)
__global__ __launch_bounds__(256) void proj_fold_k(const float* __restrict__ MF,
                                                   const int* __restrict__ cnt,
                                                   const float* __restrict__ W,   // 64x64
                                                   const float* __restrict__ B,   // 64
                                                   const float* __restrict__ Wf,  // 64x2
                                                   float2* __restrict__ Z, int n)
{
    __shared__ float Wsh[D * D];
    __shared__ float Bsh[D];
    __shared__ float Wf0[D], Wf1[D];
    for (int i = threadIdx.x; i < D * D; i += 256) Wsh[i] = W[i];
    if (threadIdx.x < D) {
        Bsh[threadIdx.x] = B[threadIdx.x];
        Wf0[threadIdx.x] = Wf[threadIdx.x * 2 + 0];
        Wf1[threadIdx.x] = Wf[threadIdx.x * 2 + 1];
    }
    __syncthreads();

    int row = blockIdx.x * 256 + threadIdx.x;
    if (row >= n) return;

    int deg = __ldg(&cnt[row]);
    float bias = (deg > 0) ? 1.0f : 0.0f;

    float acc[D];
#pragma unroll
    for (int c = 0; c < D; ++c) acc[c] = bias * Bsh[c];

    const float4* xr = reinterpret_cast<const float4*>(MF + (size_t)row * D);
    for (int k4 = 0; k4 < D / 4; ++k4) {
        float4 xv = __ldg(xr + k4);
#pragma unroll
        for (int kk = 0; kk < 4; ++kk) {
            float xk = (kk == 0) ? xv.x : (kk == 1) ? xv.y : (kk == 2) ? xv.z : xv.w;
            const float4* wr = reinterpret_cast<const float4*>(Wsh + (k4 * 4 + kk) * D);
#pragma unroll
            for (int c4 = 0; c4 < D / 4; ++c4) {
                float4 wv = wr[c4];
                acc[c4 * 4 + 0] += xk * wv.x;
                acc[c4 * 4 + 1] += xk * wv.y;
                acc[c4 * 4 + 2] += xk * wv.z;
                acc[c4 * 4 + 3] += xk * wv.w;
            }
        }
    }

    float z0 = 0.f, z1 = 0.f;
#pragma unroll
    for (int c = 0; c < D; ++c) {
        float h = lrelu(acc[c]);
        z0 += h * Wf0[c];
        z1 += h * Wf1[c];
    }
    Z[row] = make_float2(z0, z1);
}

// per edge: ACC[dst] += Z[src]   (2-float payload, red.global v2)
__global__ __launch_bounds__(256) void scatter2_k(const float2* __restrict__ Z,
                                                  const int* __restrict__ src,
                                                  const int* __restrict__ dst,
                                                  float2* __restrict__ ACC, int e)
{
    for (int i = blockIdx.x * blockDim.x + threadIdx.x; i < e;
         i += gridDim.x * blockDim.x) {
        int sidx = __ldg(&src[i]);
        int didx = __ldg(&dst[i]);
        float2 v = __ldg(&Z[sidx]);
        float* q = reinterpret_cast<float*>(ACC + didx);
        asm volatile("red.global.add.v2.f32 [%0], {%1, %2};"
                     :: "l"(q), "f"(v.x), "f"(v.y) : "memory");
    }
}

// out[t] = acc1*inv1 + cU*(deg1>0) + acc2*inv2 + cD*(deg2>0) + bc
__global__ __launch_bounds__(256) void combine_k(const float2* __restrict__ A1,
                                                 const float2* __restrict__ A2,
                                                 const int* __restrict__ c1,
                                                 const int* __restrict__ c2,
                                                 const float* __restrict__ cvec,
                                                 const float* __restrict__ bc,
                                                 float2* __restrict__ out, int n)
{
    int i = blockIdx.x * 256 + threadIdx.x;
    if (i >= n) return;
    int d1 = __ldg(&c1[i]);
    int d2 = __ldg(&c2[i]);
    float inv1 = 1.0f / (float)(d1 > 0 ? d1 : 1);
    float inv2 = 1.0f / (float)(d2 > 0 ? d2 : 1);
    float g1 = (d1 > 0) ? 1.0f : 0.0f;
    float g2 = (d2 > 0) ? 1.0f : 0.0f;
    float2 a1 = __ldg(&A1[i]);
    float2 a2 = __ldg(&A2[i]);
    float2 r;
    r.x = a1.x * inv1 + g1 * __ldg(&cvec[0]) + a2.x * inv2 + g2 * __ldg(&cvec[2]) + __ldg(&bc[0]);
    r.y = a1.y * inv1 + g1 * __ldg(&cvec[1]) + a2.y * inv2 + g2 * __ldg(&cvec[3]) + __ldg(&bc[1]);
    out[i] = r;
}

// ---------------- launch ----------------

static inline int cdiv(long long a, int b) { return (int)((a + b - 1) / b); }

static void build_csr(const int* dst, int* cnt, int* off, int* cur, int* bsum,
                      int* eidx, const int* src, int n, int e, cudaStream_t s)
{
    count_k<<<1184, 256, 0, s>>>(dst, cnt, e);
    int nb = cdiv(n, SCAN_B);
    scan_blocks_k<<<nb, SCAN_B, 0, s>>>(cnt, off, bsum, n);
    scan_sums_k<<<1, SCAN_B, 0, s>>>(bsum, nb);
    scan_add_k<<<nb, SCAN_B, 0, s>>>(off, bsum, n);
    fill_k<<<1184, 256, 0, s>>>(src, dst, off, cur, eidx, e);
}

extern "C" void kernel_launch(void* const* d_in, const int* in_sizes, int n_in,
                              void* d_out, int out_size)
{
    const float* features = (const float*)d_in[0];
    const float* W0 = (const float*)d_in[3];
    const float* b0 = (const float*)d_in[4];
    const float* W1 = (const float*)d_in[5];
    const float* b1 = (const float*)d_in[6];
    const float* Wc = (const float*)d_in[7];
    const float* bc = (const float*)d_in[8];
    const int* src_u2t = (const int*)d_in[9];
    const int* dst_u2t = (const int*)d_in[10];
    const int* src_t2u = (const int*)d_in[11];
    const int* dst_t2u = (const int*)d_in[12];
    const int* src_d2t = (const int*)d_in[13];
    const int* dst_d2t = (const int*)d_in[14];
    const int* src_t2d = (const int*)d_in[15];
    const int* dst_t2d = (const int*)d_in[16];

    const int nt = in_sizes[0] / D;
    const int nu = in_sizes[1] / D;
    const int nd = in_sizes[2] / D;
    const int e_u2t = in_sizes[9];
    const int e_t2u = in_sizes[11];
    const int e_d2t = in_sizes[13];
    const int e_t2d = in_sizes[15];

    float *mf_u, *mf_d, *Wf, *cvec;
    float2 *z_u, *z_d, *acc_t1, *acc_t2;
    int *eidx_t2u, *eidx_t2d;
    int *cnt_u, *off_u, *cur_u, *cnt_d, *off_d, *cur_d;
    int *cnt_t1, *cnt_t2, *bsum;
    cudaGetSymbolAddress((void**)&mf_u, g_mf_u);
    cudaGetSymbolAddress((void**)&mf_d, g_mf_d);
    cudaGetSymbolAddress((void**)&z_u, g_z_u);
    cudaGetSymbolAddress((void**)&z_d, g_z_d);
    cudaGetSymbolAddress((void**)&acc_t1, g_acc_t1);
    cudaGetSymbolAddress((void**)&acc_t2, g_acc_t2);
    cudaGetSymbolAddress((void**)&eidx_t2u, g_eidx_t2u);
    cudaGetSymbolAddress((void**)&eidx_t2d, g_eidx_t2d);
    cudaGetSymbolAddress((void**)&cnt_u, g_cnt_u);
    cudaGetSymbolAddress((void**)&off_u, g_off_u);
    cudaGetSymbolAddress((void**)&cur_u, g_cur_u);
    cudaGetSymbolAddress((void**)&cnt_d, g_cnt_d);
    cudaGetSymbolAddress((void**)&off_d, g_off_d);
    cudaGetSymbolAddress((void**)&cur_d, g_cur_d);
    cudaGetSymbolAddress((void**)&cnt_t1, g_cnt_t1);
    cudaGetSymbolAddress((void**)&cnt_t2, g_cnt_t2);
    cudaGetSymbolAddress((void**)&bsum, g_bsum);
    cudaGetSymbolAddress((void**)&Wf, g_Wf);
    cudaGetSymbolAddress((void**)&cvec, g_cvec);

    cudaStream_t s = 0;

    // zero counts/cursors/accumulators
    cudaMemsetAsync(cnt_u, 0, (size_t)nu * sizeof(int), s);
    cudaMemsetAsync(cur_u, 0, (size_t)nu * sizeof(int), s);
    cudaMemsetAsync(cnt_d, 0, (size_t)nd * sizeof(int), s);
    cudaMemsetAsync(cur_d, 0, (size_t)nd * sizeof(int), s);
    cudaMemsetAsync(cnt_t1, 0, (size_t)nt * sizeof(int), s);
    cudaMemsetAsync(cnt_t2, 0, (size_t)nt * sizeof(int), s);
    cudaMemsetAsync(acc_t1, 0, (size_t)nt * sizeof(float2), s);
    cudaMemsetAsync(acc_t2, 0, (size_t)nt * sizeof(float2), s);

    // fold W1@Wc, b1@Wc
    prep_k<<<1, 256, 0, s>>>(W1, b1, Wc, Wf, cvec);

    // CSR builds only for layer-0 relations
    build_csr(dst_t2u, cnt_u, off_u, cur_u, bsum, eidx_t2u, src_t2u, nu, e_t2u, s);
    build_csr(dst_t2d, cnt_d, off_d, cur_d, bsum, eidx_t2d, src_t2d, nd, e_t2d, s);

    // in-degree counts for target nodes (needed for means + bias gating)
    count_k<<<1184, 256, 0, s>>>(dst_u2t, cnt_t1, e_u2t);
    count_k<<<1184, 256, 0, s>>>(dst_d2t, cnt_t2, e_d2t);

    // layer-0 aggregation of RAW features (linear: mean before project)
    gather_mean_k<<<cdiv((long long)nu * 16, 256), 256, 0, s>>>(features, off_u, cnt_u, eidx_t2u, mf_u, nu);
    gather_mean_k<<<cdiv((long long)nd * 16, 256), 256, 0, s>>>(features, off_d, cnt_d, eidx_t2d, mf_d, nd);

    // fused: project + bias(gated) + lrelu + folded classifier weights -> 2 floats/node
    proj_fold_k<<<cdiv(nu, 256), 256, 0, s>>>(mf_u, cnt_u, W0 + 1 * D * D, b0 + 1 * D, Wf + 0,     z_u, nu);
    proj_fold_k<<<cdiv(nd, 256), 256, 0, s>>>(mf_d, cnt_d, W0 + 3 * D * D, b0 + 3 * D, Wf + D * 2, z_d, nd);

    // layer-1 aggregation as tiny-payload atomic scatter
    scatter2_k<<<1184, 256, 0, s>>>(z_u, src_u2t, dst_u2t, acc_t1, e_u2t);
    scatter2_k<<<1184, 256, 0, s>>>(z_d, src_d2t, dst_d2t, acc_t2, e_d2t);

    // final combine
    combine_k<<<cdiv(nt, 256), 256, 0, s>>>(acc_t1, acc_t2, cnt_t1, cnt_t2, cvec, bc,
                                            (float2*)d_out, nt);
}